// round 6
// baseline (speedup 1.0000x reference)
#include <cuda_runtime.h>
#include <cuda_bf16.h>
#include <math.h>
#include <stdint.h>

#define SEQ   32768
#define DM    512
#define NCH   256
#define TCH   128

// ---------------- scratch (device globals) -----------------------------------
__device__ float g_xr  [(size_t)SEQ * 1024];   // in_proj output (xs | res)
__device__ float g_u   [(size_t)SEQ * DM];     // conv+silu output
__device__ float g_xdbl[(size_t)SEQ * 36];     // x_proj output
__device__ float g_dp  [(size_t)SEQ * DM];     // delta_p
__device__ float g_P   [NCH * 1024];
__device__ float g_S   [NCH * 1024];
__device__ float g_H   [NCH * 1024];

// bf16 split operands for tensor GEMMs
__device__ __nv_bfloat16 g_xh [(size_t)SEQ * DM], g_xl [(size_t)SEQ * DM];
__device__ __nv_bfloat16 g_uh [(size_t)SEQ * DM], g_ul [(size_t)SEQ * DM];
__device__ __nv_bfloat16 g_dh [(size_t)SEQ * DM], g_dl [(size_t)SEQ * DM];
__device__ __nv_bfloat16 g_yh [(size_t)SEQ * DM], g_yl [(size_t)SEQ * DM];
__device__ __nv_bfloat16 g_wih[1024 * 512],       g_wil[1024 * 512];
__device__ __nv_bfloat16 g_dsh[512 * 512],        g_dsl[512 * 512];          // dis^T
__device__ __nv_bfloat16 g_woh[512 * 512],        g_wol[512 * 512];
__device__ __nv_bfloat16 g_xph[128 * 512],        g_xpl[128 * 512];          // x_proj_w padded

// ---------------- PTX helpers ---------------------------------------------------
__device__ __forceinline__ uint32_t smem_u32(const void* p) {
    uint32_t a;
    asm("{ .reg .u64 t; cvta.to.shared.u64 t, %1; cvt.u32.u64 %0, t; }" : "=r"(a) : "l"(p));
    return a;
}
#define CP_ASYNC16(dst, src) \
    asm volatile("cp.async.cg.shared.global [%0], [%1], 16;" :: "r"(dst), "l"(src) : "memory")
#define CP_COMMIT() asm volatile("cp.async.commit_group;" ::: "memory")
#define CP_WAIT2()  asm volatile("cp.async.wait_group 2;" ::: "memory")

__device__ __forceinline__ void ldsm4(uint32_t* r, uint32_t addr) {
    asm volatile("ldmatrix.sync.aligned.m8n8.x4.shared.b16 {%0,%1,%2,%3}, [%4];"
                 : "=r"(r[0]), "=r"(r[1]), "=r"(r[2]), "=r"(r[3]) : "r"(addr));
}
__device__ __forceinline__ void mma16816(float* c, const uint32_t* a,
                                         uint32_t b0, uint32_t b1) {
    asm volatile("mma.sync.aligned.m16n8k16.row.col.f32.bf16.bf16.f32 "
                 "{%0,%1,%2,%3}, {%4,%5,%6,%7}, {%8,%9}, {%0,%1,%2,%3};"
                 : "+f"(c[0]), "+f"(c[1]), "+f"(c[2]), "+f"(c[3])
                 : "r"(a[0]), "r"(a[1]), "r"(a[2]), "r"(a[3]), "r"(b0), "r"(b1));
}

// ---------------- math helpers --------------------------------------------------
__device__ __forceinline__ float softplusf(float x) {
    float ax = fabsf(x);
    if (ax < 0.25f) {
        float x2 = x * x;
        return 0.69314718055994531f + 0.5f * x
             + x2 * (0.125f + x2 * (-1.0f/192.0f + x2 * (1.0f/2880.0f)));
    }
    return fmaxf(x, 0.0f) + log1pf(expf(-ax));
}
__device__ __forceinline__ float siluf(float x) { return x / (1.0f + __expf(-x)); }
__device__ __forceinline__ void split_bf16(float v, __nv_bfloat16& h, __nv_bfloat16& l) {
    h = __float2bfloat16(v);
    l = __float2bfloat16(v - __bfloat162float(h));
}

// ---------------- combined split conversion kernel ------------------------------
__global__ __launch_bounds__(256)
void cvt_all(const float* __restrict__ x, const float* __restrict__ inw,
             const float* __restrict__ outw, const float* __restrict__ dis,
             const float* __restrict__ xpw)
{
    int b = blockIdx.x;
    if (b < 16384) {
        int i = b * 256 + threadIdx.x;
        float4 v = reinterpret_cast<const float4*>(x)[i];
        __nv_bfloat16 h[4], l[4];
        split_bf16(v.x, h[0], l[0]); split_bf16(v.y, h[1], l[1]);
        split_bf16(v.z, h[2], l[2]); split_bf16(v.w, h[3], l[3]);
        reinterpret_cast<uint2*>(g_xh)[i] = *reinterpret_cast<uint2*>(h);
        reinterpret_cast<uint2*>(g_xl)[i] = *reinterpret_cast<uint2*>(l);
    } else if (b < 16896) {
        int i = (b - 16384) * 256 + threadIdx.x;
        float4 v = reinterpret_cast<const float4*>(inw)[i];
        __nv_bfloat16 h[4], l[4];
        split_bf16(v.x, h[0], l[0]); split_bf16(v.y, h[1], l[1]);
        split_bf16(v.z, h[2], l[2]); split_bf16(v.w, h[3], l[3]);
        reinterpret_cast<uint2*>(g_wih)[i] = *reinterpret_cast<uint2*>(h);
        reinterpret_cast<uint2*>(g_wil)[i] = *reinterpret_cast<uint2*>(l);
    } else if (b < 17152) {
        int i = (b - 16896) * 256 + threadIdx.x;
        float4 v = reinterpret_cast<const float4*>(outw)[i];
        __nv_bfloat16 h[4], l[4];
        split_bf16(v.x, h[0], l[0]); split_bf16(v.y, h[1], l[1]);
        split_bf16(v.z, h[2], l[2]); split_bf16(v.w, h[3], l[3]);
        reinterpret_cast<uint2*>(g_woh)[i] = *reinterpret_cast<uint2*>(h);
        reinterpret_cast<uint2*>(g_wol)[i] = *reinterpret_cast<uint2*>(l);
    } else if (b < 18176) {
        int idx = (b - 17152) * 256 + threadIdx.x;   // out[n][k] = dis[k][n]
        int n = idx >> 9, k = idx & 511;
        __nv_bfloat16 h, l;
        split_bf16(dis[k * 512 + n], h, l);
        g_dsh[idx] = h; g_dsl[idx] = l;
    } else {
        int idx = (b - 18176) * 256 + threadIdx.x;   // 128x512 padded
        int r = idx >> 9;
        __nv_bfloat16 h = __float2bfloat16(0.0f), l = h;
        if (r < 36) split_bf16(xpw[idx], h, l);
        g_xph[idx] = h; g_xpl[idx] = l;
    }
}

// ---------------- mma.sync split-bf16 GEMM ---------------------------------------
// C[M,N] = (Ah+Al)[M,K] @ (Bh+Bl)[N,K]^T ; fp32 accum.
// CTA tile 128m x 128n, BK=16, 4-stage cp.async ring, 1 barrier/stage.
// 8 warps (4m x 2n), warp tile 32x64.
// Stage layout: Ah(6144) Al(6144) Bh(6144) Bl(6144) @ PITCH=48 -> 24576B.
// EPI: 0 plain store, 1 finite filter, 2 narrow store (cols < ldc only)
#define PITCH   48
#define STAGE_B 24576
template <int EPI>
__global__ __launch_bounds__(256, 2)
void mma_gemm(const __nv_bfloat16* __restrict__ Ah, const __nv_bfloat16* __restrict__ Al,
              const __nv_bfloat16* __restrict__ Bh, const __nv_bfloat16* __restrict__ Bl,
              float* __restrict__ C, int N, int K, int ldc)
{
    extern __shared__ char dsm[];
    const uint32_t sb = smem_u32(dsm);
    const int tid = threadIdx.x;
    const int wid = tid >> 5, L = tid & 31;
    const int wm = wid >> 1, wn = wid & 1;
    const int m0 = blockIdx.y * 128, n0 = blockIdx.x * 128;

    const __nv_bfloat16* srcs[4] = {
        Ah + (size_t)m0 * K, Al + (size_t)m0 * K,
        Bh + (size_t)n0 * K, Bl + (size_t)n0 * K };

    const int lrow = L & 15;
    const int lcolB = (L >> 4) * 16;
    const uint32_t aBase = sb + (wm * 32 + lrow) * PITCH + lcolB;            // Ah @ 0
    const uint32_t bBase = sb + 12288 + (wn * 64 + lrow) * PITCH + lcolB;    // Bh @ 12288

    float acc[2][8][4];
    #pragma unroll
    for (int i = 0; i < 2; i++)
        #pragma unroll
        for (int j = 0; j < 8; j++)
            #pragma unroll
            for (int q = 0; q < 4; q++) acc[i][j][q] = 0.0f;

    const int nk = K / 16;

    // stage loader: 1024 16B-chunks (4 mats x 128 rows x 2), 4 per thread
    auto load_stage = [&](int ks) {
        uint32_t dst0 = sb + (ks & 3) * STAGE_B;
        int k0 = ks * 16;
        #pragma unroll
        for (int it = 0; it < 4; it++) {
            int cid = it * 256 + tid;
            int mat = cid >> 8, w = cid & 255;
            int r = w >> 1, c = w & 1;
            uint32_t dst = dst0 + mat * 6144 + r * PITCH + c * 16;
            const __nv_bfloat16* src = srcs[mat] + (size_t)r * K + k0 + c * 8;
            CP_ASYNC16(dst, src);
        }
    };

    load_stage(0); CP_COMMIT();
    load_stage(1); CP_COMMIT();
    load_stage(2); CP_COMMIT();

    for (int ks = 0; ks < nk; ks++) {
        CP_WAIT2();
        __syncthreads();
        if (ks + 3 < nk) load_stage(ks + 3);
        CP_COMMIT();

        uint32_t bo = (ks & 3) * STAGE_B;
        uint32_t ah[2][4], al[2][4], b[4][4];
        #pragma unroll
        for (int mi = 0; mi < 2; mi++) {
            ldsm4(ah[mi], aBase + bo +        mi * 768);
            ldsm4(al[mi], aBase + bo + 6144 + mi * 768);
        }
        #pragma unroll
        for (int t = 0; t < 4; t++)
            ldsm4(b[t], bBase + bo + t * 768);
        #pragma unroll
        for (int mi = 0; mi < 2; mi++)
            #pragma unroll
            for (int t = 0; t < 4; t++) {
                mma16816(acc[mi][2*t+0], ah[mi], b[t][0], b[t][2]);
                mma16816(acc[mi][2*t+1], ah[mi], b[t][1], b[t][3]);
                mma16816(acc[mi][2*t+0], al[mi], b[t][0], b[t][2]);
                mma16816(acc[mi][2*t+1], al[mi], b[t][1], b[t][3]);
            }
        #pragma unroll
        for (int t = 0; t < 4; t++)
            ldsm4(b[t], bBase + bo + 6144 + t * 768);   // Bl
        #pragma unroll
        for (int mi = 0; mi < 2; mi++)
            #pragma unroll
            for (int t = 0; t < 4; t++) {
                mma16816(acc[mi][2*t+0], ah[mi], b[t][0], b[t][2]);
                mma16816(acc[mi][2*t+1], ah[mi], b[t][1], b[t][3]);
            }
    }

    // epilogue
    #pragma unroll
    for (int mi = 0; mi < 2; mi++) {
        #pragma unroll
        for (int j = 0; j < 8; j++) {
            int row = m0 + wm * 32 + mi * 16 + (L >> 2);
            int col = n0 + wn * 64 + j * 8 + (L & 3) * 2;
            float v0 = acc[mi][j][0], v1 = acc[mi][j][1];
            float v2 = acc[mi][j][2], v3 = acc[mi][j][3];
            if (EPI == 1) {
                v0 = isfinite(v0) ? v0 : 0.0f; v1 = isfinite(v1) ? v1 : 0.0f;
                v2 = isfinite(v2) ? v2 : 0.0f; v3 = isfinite(v3) ? v3 : 0.0f;
            }
            if (EPI == 2) {
                if (col + 1 < ldc) {
                    *reinterpret_cast<float2*>(C + (size_t)row * ldc + col)       = make_float2(v0, v1);
                    *reinterpret_cast<float2*>(C + (size_t)(row + 8) * ldc + col) = make_float2(v2, v3);
                }
            } else {
                *reinterpret_cast<float2*>(C + (size_t)row * ldc + col)       = make_float2(v0, v1);
                *reinterpret_cast<float2*>(C + (size_t)(row + 8) * ldc + col) = make_float2(v2, v3);
            }
        }
    }
}

// ---------------- SIMT GEMM (dt_proj: K=32, softplus, bf16-split output) --------
__global__ __launch_bounds__(256)
void dtproj_kernel(const float* __restrict__ A,      // g_xdbl, lda=36
                   const float* __restrict__ B,      // dt_proj_w [512,32]
                   const float* __restrict__ bias,
                   __nv_bfloat16* __restrict__ Chi,
                   __nv_bfloat16* __restrict__ Clo)
{
    __shared__ float As[8][128];
    __shared__ float Bs[8][128];
    const int tid = threadIdx.x;
    const int m0 = blockIdx.y * 128, n0 = blockIdx.x * 128;
    const int tr = tid / 16, tc = tid % 16;
    const int K = 32, N = 512, lda = 36;

    float acc[8][8];
    #pragma unroll
    for (int i = 0; i < 8; i++)
        #pragma unroll
        for (int j = 0; j < 8; j++) acc[i][j] = 0.0f;

    for (int k0 = 0; k0 < K; k0 += 8) {
        {
            int row = tid >> 1, kq = (tid & 1) * 4;
            float4 v = *reinterpret_cast<const float4*>(A + (size_t)(m0 + row) * lda + k0 + kq);
            As[kq+0][row] = v.x; As[kq+1][row] = v.y; As[kq+2][row] = v.z; As[kq+3][row] = v.w;
        }
        {
            int row = tid >> 1, kq = (tid & 1) * 4;
            float4 v = *reinterpret_cast<const float4*>(B + (size_t)(n0 + row) * K + k0 + kq);
            Bs[kq+0][row] = v.x; Bs[kq+1][row] = v.y; Bs[kq+2][row] = v.z; Bs[kq+3][row] = v.w;
        }
        __syncthreads();
        #pragma unroll
        for (int k = 0; k < 8; k++) {
            float ra[8], rb[8];
            *reinterpret_cast<float4*>(&ra[0]) = *reinterpret_cast<const float4*>(&As[k][tr*8]);
            *reinterpret_cast<float4*>(&ra[4]) = *reinterpret_cast<const float4*>(&As[k][tr*8+4]);
            *reinterpret_cast<float4*>(&rb[0]) = *reinterpret_cast<const float4*>(&Bs[k][tc*8]);
            *reinterpret_cast<float4*>(&rb[4]) = *reinterpret_cast<const float4*>(&Bs[k][tc*8+4]);
            #pragma unroll
            for (int i = 0; i < 8; i++)
                #pragma unroll
                for (int j = 0; j < 8; j++)
                    acc[i][j] = fmaf(ra[i], rb[j], acc[i][j]);
        }
        __syncthreads();
    }
    #pragma unroll
    for (int i = 0; i < 8; i++) {
        size_t m = (size_t)(m0 + tr * 8 + i);
        __nv_bfloat16 ho[8], lo[8];
        #pragma unroll
        for (int j = 0; j < 8; j++) {
            float v = softplusf(acc[i][j] + bias[n0 + tc * 8 + j]);
            split_bf16(v, ho[j], lo[j]);
        }
        *reinterpret_cast<uint4*>(Chi + m * N + n0 + tc * 8) = *reinterpret_cast<uint4*>(ho);
        *reinterpret_cast<uint4*>(Clo + m * N + n0 + tc * 8) = *reinterpret_cast<uint4*>(lo);
    }
}

// ---------------- depthwise conv + silu (+ bf16 split of u) ----------------------
__global__ __launch_bounds__(256)
void conv_silu_kernel(const float* __restrict__ cw, const float* __restrict__ cb)
{
    int idx = blockIdx.x * 256 + threadIdx.x;
    int t = idx >> 9, d = idx & 511;
    float4 w = reinterpret_cast<const float4*>(cw)[d];
    float acc = cb[d];
    const float* xs = g_xr + d;
    acc = fmaf(w.w, xs[(size_t)t * 1024], acc);
    if (t >= 1) acc = fmaf(w.z, xs[(size_t)(t-1) * 1024], acc);
    if (t >= 2) acc = fmaf(w.y, xs[(size_t)(t-2) * 1024], acc);
    if (t >= 3) acc = fmaf(w.x, xs[(size_t)(t-3) * 1024], acc);
    float u = siluf(acc);
    g_u[idx] = u;
    __nv_bfloat16 h, l;
    split_bf16(u, h, l);
    g_uh[idx] = h;
    g_ul[idx] = l;
}

// ---------------- scan passes -------------------------------------------------------
__global__ __launch_bounds__(128)
void scanA_kernel(const float* __restrict__ Alog)
{
    int d = blockIdx.x * 128 + threadIdx.x;
    int c = blockIdx.y;
    float A0 = -expf(Alog[d * 2 + 0]);
    float A1 = -expf(Alog[d * 2 + 1]);
    float P0 = 1.f, P1 = 1.f, S0 = 0.f, S1 = 0.f;
    const float* dp = g_dp + (size_t)c * TCH * DM + d;
    const float* uu = g_u  + (size_t)c * TCH * DM + d;
    const float* xd = g_xdbl + (size_t)c * TCH * 36;
    #pragma unroll 4
    for (int i = 0; i < TCH; i++) {
        float dpv = dp[(size_t)i * DM];
        float uv  = uu[(size_t)i * DM];
        float B0 = xd[i * 36 + 32], B1 = xd[i * 36 + 33];
        float x0 = dpv * A0, x1 = dpv * A1;
        float a0 = 0.f, a1 = 0.f;
        if (fmaxf(x0, x1) > -87.0f) { a0 = __expf(x0); a1 = __expf(x1); }
        S0 = fmaf(a0, S0, dpv * B0 * uv);
        S1 = fmaf(a1, S1, dpv * B1 * uv);
        P0 *= a0; P1 *= a1;
    }
    int dn = d * 2;
    g_P[c * 1024 + dn] = P0; g_P[c * 1024 + dn + 1] = P1;
    g_S[c * 1024 + dn] = S0; g_S[c * 1024 + dn + 1] = S1;
}

__global__ __launch_bounds__(128)
void scanB_kernel()
{
    int dn = blockIdx.x * 128 + threadIdx.x;
    float h = 0.0f;
    for (int cb = 0; cb < NCH; cb += 16) {
        float p[16], s[16];
        #pragma unroll
        for (int i = 0; i < 16; i++) {
            p[i] = g_P[(cb + i) * 1024 + dn];
            s[i] = g_S[(cb + i) * 1024 + dn];
        }
        #pragma unroll
        for (int i = 0; i < 16; i++) {
            g_H[(cb + i) * 1024 + dn] = h;
            h = fmaf(p[i], h, s[i]);
        }
    }
}

__global__ __launch_bounds__(128)
void scanC_kernel(const float* __restrict__ Alog, const float* __restrict__ Dw)
{
    int d = blockIdx.x * 128 + threadIdx.x;
    int c = blockIdx.y;
    float A0 = -expf(Alog[d * 2 + 0]);
    float A1 = -expf(Alog[d * 2 + 1]);
    float Dv = Dw[d];
    float h0 = g_H[c * 1024 + d * 2];
    float h1 = g_H[c * 1024 + d * 2 + 1];
    const float* dp = g_dp + (size_t)c * TCH * DM + d;
    const float* uu = g_u  + (size_t)c * TCH * DM + d;
    const float* xd = g_xdbl + (size_t)c * TCH * 36;
    const float* rs = g_xr + (size_t)c * TCH * 1024 + 512 + d;
    __nv_bfloat16* yh = g_yh + (size_t)c * TCH * DM + d;
    __nv_bfloat16* yl = g_yl + (size_t)c * TCH * DM + d;
    #pragma unroll 4
    for (int i = 0; i < TCH; i++) {
        float dpv = dp[(size_t)i * DM];
        float uv  = uu[(size_t)i * DM];
        float B0 = xd[i * 36 + 32], B1 = xd[i * 36 + 33];
        float C0 = xd[i * 36 + 34], C1 = xd[i * 36 + 35];
        float x0 = dpv * A0, x1 = dpv * A1;
        float a0 = 0.f, a1 = 0.f;
        if (fmaxf(x0, x1) > -87.0f) { a0 = __expf(x0); a1 = __expf(x1); }
        h0 = fmaf(a0, h0, dpv * B0 * uv);
        h1 = fmaf(a1, h1, dpv * B1 * uv);
        float y = fmaf(h0, C0, fmaf(h1, C1, uv * Dv));
        y *= siluf(rs[(size_t)i * 1024]);
        __nv_bfloat16 h, l;
        split_bf16(y, h, l);
        yh[(size_t)i * DM] = h;
        yl[(size_t)i * DM] = l;
    }
}

// ---------------- launch --------------------------------------------------------
extern "C" void kernel_launch(void* const* d_in, const int* in_sizes, int n_in,
                              void* d_out, int out_size)
{
    const float* x     = (const float*)d_in[0];
    const float* dis   = (const float*)d_in[1];
    const float* inw   = (const float*)d_in[2];
    const float* convw = (const float*)d_in[3];
    const float* convb = (const float*)d_in[4];
    const float* xpw   = (const float*)d_in[5];
    const float* dtw   = (const float*)d_in[6];
    const float* dtb   = (const float*)d_in[7];
    const float* alog  = (const float*)d_in[8];
    const float* Dw    = (const float*)d_in[9];
    const float* outw  = (const float*)d_in[10];
    float* out = (float*)d_out;

    float *xr, *dp, *xdbl;
    __nv_bfloat16 *xh, *xl, *uh, *ul, *dh, *dl, *yh, *yl;
    __nv_bfloat16 *wih, *wil, *dsh, *dsl, *woh, *wol, *xph, *xpl;
    cudaGetSymbolAddress((void**)&xr,   g_xr);
    cudaGetSymbolAddress((void**)&dp,   g_dp);
    cudaGetSymbolAddress((void**)&xdbl, g_xdbl);
    cudaGetSymbolAddress((void**)&xh,  g_xh);  cudaGetSymbolAddress((void**)&xl,  g_xl);
    cudaGetSymbolAddress((void**)&uh,  g_uh);  cudaGetSymbolAddress((void**)&ul,  g_ul);
    cudaGetSymbolAddress((void**)&dh,  g_dh);  cudaGetSymbolAddress((void**)&dl,  g_dl);
    cudaGetSymbolAddress((void**)&yh,  g_yh);  cudaGetSymbolAddress((void**)&yl,  g_yl);
    cudaGetSymbolAddress((void**)&wih, g_wih); cudaGetSymbolAddress((void**)&wil, g_wil);
    cudaGetSymbolAddress((void**)&dsh, g_dsh); cudaGetSymbolAddress((void**)&dsl, g_dsl);
    cudaGetSymbolAddress((void**)&woh, g_woh); cudaGetSymbolAddress((void**)&wol, g_wol);
    cudaGetSymbolAddress((void**)&xph, g_xph); cudaGetSymbolAddress((void**)&xpl, g_xpl);

    const int GEMM_SMEM = 4 * STAGE_B;   // 98304
    cudaFuncSetAttribute(mma_gemm<0>, cudaFuncAttributeMaxDynamicSharedMemorySize, GEMM_SMEM);
    cudaFuncSetAttribute(mma_gemm<1>, cudaFuncAttributeMaxDynamicSharedMemorySize, GEMM_SMEM);
    cudaFuncSetAttribute(mma_gemm<2>, cudaFuncAttributeMaxDynamicSharedMemorySize, GEMM_SMEM);

    // 0) all split conversions (x, in_proj_w, out_proj_w, dis^T, x_proj_w padded)
    cvt_all<<<18432, 256>>>(x, inw, outw, dis, xpw);

    // 1) xr = x @ in_proj_w^T   [32768 x 1024]
    mma_gemm<0><<<dim3(8, SEQ / 128), 256, GEMM_SMEM>>>(xh, xl, wih, wil, xr, 1024, 512, 1024);

    // 2) u = silu(conv(xs))  (+ bf16 split)
    conv_silu_kernel<<<(SEQ * DM) / 256, 256>>>(convw, convb);

    // 3) xdbl = u @ x_proj_w^T  (tensor core, N padded to 128, store cols<36)
    mma_gemm<2><<<dim3(1, SEQ / 128), 256, GEMM_SMEM>>>(uh, ul, xph, xpl, xdbl, 128, 512, 36);

    // 4) delta = softplus(xdbl[:, :32] @ dt_proj_w^T + b) -> bf16 split
    dtproj_kernel<<<dim3(DM / 128, SEQ / 128), 256>>>(g_xdbl, dtw, dtb, dh, dl);

    // 5) delta_p = delta @ dis_dense  (dis pre-transposed to [N,K])
    mma_gemm<0><<<dim3(DM / 128, SEQ / 128), 256, GEMM_SMEM>>>(dh, dl, dsh, dsl, dp, DM, 512, DM);

    // 6-8) chunked selective scan
    scanA_kernel<<<dim3(4, NCH), 128>>>(alog);
    scanB_kernel<<<8, 128>>>();
    scanC_kernel<<<dim3(4, NCH), 128>>>(alog, Dw);

    // 9) out = y @ out_proj_w^T, finite filter
    mma_gemm<1><<<dim3(DM / 128, SEQ / 128), 256, GEMM_SMEM>>>(yh, yl, woh, wol, out, DM, 512, DM);
}

// round 7
// speedup vs baseline: 1.1412x; 1.1412x over previous
#include <cuda_runtime.h>
#include <cuda_bf16.h>
#include <math.h>
#include <stdint.h>

#define SEQ   32768
#define DM    512
#define NCH   512
#define TCH   64

// ---------------- scratch (device globals) -----------------------------------
__device__ float g_xr  [(size_t)SEQ * 1024];   // in_proj output (xs | res)
__device__ float g_u   [(size_t)SEQ * DM];     // conv+silu output
__device__ float g_xdbl[(size_t)SEQ * 36];     // x_proj output
__device__ float g_dp  [(size_t)SEQ * DM];     // delta_p
__device__ float g_P   [NCH * 1024];
__device__ float g_S   [NCH * 1024];
__device__ float g_H   [NCH * 1024];

// bf16 split operands for tensor GEMMs
__device__ __nv_bfloat16 g_xh [(size_t)SEQ * DM], g_xl [(size_t)SEQ * DM];
__device__ __nv_bfloat16 g_uh [(size_t)SEQ * DM], g_ul [(size_t)SEQ * DM];
__device__ __nv_bfloat16 g_dh [(size_t)SEQ * DM], g_dl [(size_t)SEQ * DM];
__device__ __nv_bfloat16 g_yh [(size_t)SEQ * DM], g_yl [(size_t)SEQ * DM];
__device__ __nv_bfloat16 g_wih[1024 * 512],       g_wil[1024 * 512];
__device__ __nv_bfloat16 g_dsh[512 * 512],        g_dsl[512 * 512];          // dis^T
__device__ __nv_bfloat16 g_woh[512 * 512],        g_wol[512 * 512];
__device__ __nv_bfloat16 g_xph[128 * 512],        g_xpl[128 * 512];          // x_proj_w padded

// ---------------- PTX helpers ---------------------------------------------------
__device__ __forceinline__ uint32_t smem_u32(const void* p) {
    uint32_t a;
    asm("{ .reg .u64 t; cvta.to.shared.u64 t, %1; cvt.u32.u64 %0, t; }" : "=r"(a) : "l"(p));
    return a;
}
#define CP_ASYNC16(dst, src) \
    asm volatile("cp.async.cg.shared.global [%0], [%1], 16;" :: "r"(dst), "l"(src) : "memory")
#define CP_COMMIT() asm volatile("cp.async.commit_group;" ::: "memory")
#define CP_WAIT1()  asm volatile("cp.async.wait_group 1;" ::: "memory")

__device__ __forceinline__ void ldsm4(uint32_t* r, uint32_t addr) {
    asm volatile("ldmatrix.sync.aligned.m8n8.x4.shared.b16 {%0,%1,%2,%3}, [%4];"
                 : "=r"(r[0]), "=r"(r[1]), "=r"(r[2]), "=r"(r[3]) : "r"(addr));
}
__device__ __forceinline__ void mma16816(float* c, const uint32_t* a,
                                         uint32_t b0, uint32_t b1) {
    asm volatile("mma.sync.aligned.m16n8k16.row.col.f32.bf16.bf16.f32 "
                 "{%0,%1,%2,%3}, {%4,%5,%6,%7}, {%8,%9}, {%0,%1,%2,%3};"
                 : "+f"(c[0]), "+f"(c[1]), "+f"(c[2]), "+f"(c[3])
                 : "r"(a[0]), "r"(a[1]), "r"(a[2]), "r"(a[3]), "r"(b0), "r"(b1));
}

// ---------------- math helpers --------------------------------------------------
__device__ __forceinline__ float softplusf(float x) {
    float ax = fabsf(x);
    if (ax < 0.25f) {
        float x2 = x * x;
        return 0.69314718055994531f + 0.5f * x
             + x2 * (0.125f + x2 * (-1.0f/192.0f + x2 * (1.0f/2880.0f)));
    }
    return fmaxf(x, 0.0f) + log1pf(expf(-ax));
}
__device__ __forceinline__ float siluf(float x) { return x / (1.0f + __expf(-x)); }
__device__ __forceinline__ void split_bf16(float v, __nv_bfloat16& h, __nv_bfloat16& l) {
    h = __float2bfloat16(v);
    l = __float2bfloat16(v - __bfloat162float(h));
}

// ---------------- combined split conversion kernel ------------------------------
__global__ __launch_bounds__(256)
void cvt_all(const float* __restrict__ x, const float* __restrict__ inw,
             const float* __restrict__ outw, const float* __restrict__ dis,
             const float* __restrict__ xpw)
{
    int b = blockIdx.x;
    if (b < 16384) {
        int i = b * 256 + threadIdx.x;
        float4 v = reinterpret_cast<const float4*>(x)[i];
        __nv_bfloat16 h[4], l[4];
        split_bf16(v.x, h[0], l[0]); split_bf16(v.y, h[1], l[1]);
        split_bf16(v.z, h[2], l[2]); split_bf16(v.w, h[3], l[3]);
        reinterpret_cast<uint2*>(g_xh)[i] = *reinterpret_cast<uint2*>(h);
        reinterpret_cast<uint2*>(g_xl)[i] = *reinterpret_cast<uint2*>(l);
    } else if (b < 16896) {
        int i = (b - 16384) * 256 + threadIdx.x;
        float4 v = reinterpret_cast<const float4*>(inw)[i];
        __nv_bfloat16 h[4], l[4];
        split_bf16(v.x, h[0], l[0]); split_bf16(v.y, h[1], l[1]);
        split_bf16(v.z, h[2], l[2]); split_bf16(v.w, h[3], l[3]);
        reinterpret_cast<uint2*>(g_wih)[i] = *reinterpret_cast<uint2*>(h);
        reinterpret_cast<uint2*>(g_wil)[i] = *reinterpret_cast<uint2*>(l);
    } else if (b < 17152) {
        int i = (b - 16896) * 256 + threadIdx.x;
        float4 v = reinterpret_cast<const float4*>(outw)[i];
        __nv_bfloat16 h[4], l[4];
        split_bf16(v.x, h[0], l[0]); split_bf16(v.y, h[1], l[1]);
        split_bf16(v.z, h[2], l[2]); split_bf16(v.w, h[3], l[3]);
        reinterpret_cast<uint2*>(g_woh)[i] = *reinterpret_cast<uint2*>(h);
        reinterpret_cast<uint2*>(g_wol)[i] = *reinterpret_cast<uint2*>(l);
    } else if (b < 18176) {
        int idx = (b - 17152) * 256 + threadIdx.x;   // out[n][k] = dis[k][n]
        int n = idx >> 9, k = idx & 511;
        __nv_bfloat16 h, l;
        split_bf16(dis[k * 512 + n], h, l);
        g_dsh[idx] = h; g_dsl[idx] = l;
    } else {
        int idx = (b - 18176) * 256 + threadIdx.x;   // 128x512 padded
        int r = idx >> 9;
        __nv_bfloat16 h = __float2bfloat16(0.0f), l = h;
        if (r < 36) split_bf16(xpw[idx], h, l);
        g_xph[idx] = h; g_xpl[idx] = l;
    }
}

// ---------------- mma.sync split-bf16 GEMM (R5 config: BK=32, 2 stages) ---------
// C[M,N] = (Ah+Al)[M,K] @ (Bh+Bl)[N,K]^T ; fp32 accum.
// CTA tile 128m x 128n, 8 warps (4m x 2n), warp tile 32x64.
// EPI: 0 plain store, 1 finite filter, 2 narrow store (cols < ldc only)
#define PITCH   80
#define STAGE_B 40960
template <int EPI>
__global__ __launch_bounds__(256, 2)
void mma_gemm(const __nv_bfloat16* __restrict__ Ah, const __nv_bfloat16* __restrict__ Al,
              const __nv_bfloat16* __restrict__ Bh, const __nv_bfloat16* __restrict__ Bl,
              float* __restrict__ C, int N, int K, int ldc)
{
    extern __shared__ char dsm[];
    const uint32_t sb = smem_u32(dsm);
    const int tid = threadIdx.x;
    const int wid = tid >> 5, L = tid & 31;
    const int wm = wid >> 1, wn = wid & 1;
    const int m0 = blockIdx.y * 128, n0 = blockIdx.x * 128;

    const __nv_bfloat16* srcs[4] = {
        Ah + (size_t)m0 * K, Al + (size_t)m0 * K,
        Bh + (size_t)n0 * K, Bl + (size_t)n0 * K };

    const int lrow = L & 15;
    const int lcolB = (L >> 4) * 16;
    const uint32_t aBase = sb + (wm * 32 + lrow) * PITCH + lcolB;
    const uint32_t bBase = sb + 20480 + (wn * 64 + lrow) * PITCH + lcolB;

    float acc[2][8][4];
    #pragma unroll
    for (int i = 0; i < 2; i++)
        #pragma unroll
        for (int j = 0; j < 8; j++)
            #pragma unroll
            for (int q = 0; q < 4; q++) acc[i][j][q] = 0.0f;

    const int nk = K / 32;

    auto load_stage = [&](int ks, int buf) {
        uint32_t dst0 = sb + buf * STAGE_B;
        int k0 = ks * 32;
        #pragma unroll
        for (int it = 0; it < 8; it++) {
            int cid = it * 256 + tid;
            int mat = cid >> 9, w = cid & 511;
            int r = w >> 2, c = w & 3;
            uint32_t dst = dst0 + mat * 10240 + r * PITCH + c * 16;
            const __nv_bfloat16* src = srcs[mat] + (size_t)r * K + k0 + c * 8;
            CP_ASYNC16(dst, src);
        }
    };

    load_stage(0, 0); CP_COMMIT();
    load_stage(1, 1); CP_COMMIT();

    for (int ks = 0; ks < nk; ks++) {
        CP_WAIT1();
        __syncthreads();
        uint32_t bo = (ks & 1) * STAGE_B;
        #pragma unroll
        for (int kk = 0; kk < 2; kk++) {
            uint32_t ko = kk * 32;
            uint32_t ah[2][4], al[2][4], b[4][4];
            #pragma unroll
            for (int mi = 0; mi < 2; mi++) {
                ldsm4(ah[mi], aBase + bo +         mi * 1280 + ko);
                ldsm4(al[mi], aBase + bo + 10240 + mi * 1280 + ko);
            }
            #pragma unroll
            for (int t = 0; t < 4; t++)
                ldsm4(b[t], bBase + bo + t * 1280 + ko);
            #pragma unroll
            for (int mi = 0; mi < 2; mi++)
                #pragma unroll
                for (int t = 0; t < 4; t++) {
                    mma16816(acc[mi][2*t+0], ah[mi], b[t][0], b[t][2]);
                    mma16816(acc[mi][2*t+1], ah[mi], b[t][1], b[t][3]);
                    mma16816(acc[mi][2*t+0], al[mi], b[t][0], b[t][2]);
                    mma16816(acc[mi][2*t+1], al[mi], b[t][1], b[t][3]);
                }
            #pragma unroll
            for (int t = 0; t < 4; t++)
                ldsm4(b[t], bBase + bo + 10240 + t * 1280 + ko);
            #pragma unroll
            for (int mi = 0; mi < 2; mi++)
                #pragma unroll
                for (int t = 0; t < 4; t++) {
                    mma16816(acc[mi][2*t+0], ah[mi], b[t][0], b[t][2]);
                    mma16816(acc[mi][2*t+1], ah[mi], b[t][1], b[t][3]);
                }
        }
        __syncthreads();
        if (ks + 2 < nk) load_stage(ks + 2, ks & 1);
        CP_COMMIT();
    }

    // epilogue
    #pragma unroll
    for (int mi = 0; mi < 2; mi++) {
        #pragma unroll
        for (int j = 0; j < 8; j++) {
            int row = m0 + wm * 32 + mi * 16 + (L >> 2);
            int col = n0 + wn * 64 + j * 8 + (L & 3) * 2;
            float v0 = acc[mi][j][0], v1 = acc[mi][j][1];
            float v2 = acc[mi][j][2], v3 = acc[mi][j][3];
            if (EPI == 1) {
                v0 = isfinite(v0) ? v0 : 0.0f; v1 = isfinite(v1) ? v1 : 0.0f;
                v2 = isfinite(v2) ? v2 : 0.0f; v3 = isfinite(v3) ? v3 : 0.0f;
            }
            if (EPI == 2) {
                if (col + 1 < ldc) {
                    *reinterpret_cast<float2*>(C + (size_t)row * ldc + col)       = make_float2(v0, v1);
                    *reinterpret_cast<float2*>(C + (size_t)(row + 8) * ldc + col) = make_float2(v2, v3);
                }
            } else {
                *reinterpret_cast<float2*>(C + (size_t)row * ldc + col)       = make_float2(v0, v1);
                *reinterpret_cast<float2*>(C + (size_t)(row + 8) * ldc + col) = make_float2(v2, v3);
            }
        }
    }
}

// ---------------- SIMT GEMM (dt_proj: K=32, softplus, bf16-split output) --------
__global__ __launch_bounds__(256)
void dtproj_kernel(const float* __restrict__ A,      // g_xdbl, lda=36
                   const float* __restrict__ B,      // dt_proj_w [512,32]
                   const float* __restrict__ bias,
                   __nv_bfloat16* __restrict__ Chi,
                   __nv_bfloat16* __restrict__ Clo)
{
    __shared__ float As[8][128];
    __shared__ float Bs[8][128];
    const int tid = threadIdx.x;
    const int m0 = blockIdx.y * 128, n0 = blockIdx.x * 128;
    const int tr = tid / 16, tc = tid % 16;
    const int K = 32, N = 512, lda = 36;

    float acc[8][8];
    #pragma unroll
    for (int i = 0; i < 8; i++)
        #pragma unroll
        for (int j = 0; j < 8; j++) acc[i][j] = 0.0f;

    for (int k0 = 0; k0 < K; k0 += 8) {
        {
            int row = tid >> 1, kq = (tid & 1) * 4;
            float4 v = *reinterpret_cast<const float4*>(A + (size_t)(m0 + row) * lda + k0 + kq);
            As[kq+0][row] = v.x; As[kq+1][row] = v.y; As[kq+2][row] = v.z; As[kq+3][row] = v.w;
        }
        {
            int row = tid >> 1, kq = (tid & 1) * 4;
            float4 v = *reinterpret_cast<const float4*>(B + (size_t)(n0 + row) * K + k0 + kq);
            Bs[kq+0][row] = v.x; Bs[kq+1][row] = v.y; Bs[kq+2][row] = v.z; Bs[kq+3][row] = v.w;
        }
        __syncthreads();
        #pragma unroll
        for (int k = 0; k < 8; k++) {
            float ra[8], rb[8];
            *reinterpret_cast<float4*>(&ra[0]) = *reinterpret_cast<const float4*>(&As[k][tr*8]);
            *reinterpret_cast<float4*>(&ra[4]) = *reinterpret_cast<const float4*>(&As[k][tr*8+4]);
            *reinterpret_cast<float4*>(&rb[0]) = *reinterpret_cast<const float4*>(&Bs[k][tc*8]);
            *reinterpret_cast<float4*>(&rb[4]) = *reinterpret_cast<const float4*>(&Bs[k][tc*8+4]);
            #pragma unroll
            for (int i = 0; i < 8; i++)
                #pragma unroll
                for (int j = 0; j < 8; j++)
                    acc[i][j] = fmaf(ra[i], rb[j], acc[i][j]);
        }
        __syncthreads();
    }
    #pragma unroll
    for (int i = 0; i < 8; i++) {
        size_t m = (size_t)(m0 + tr * 8 + i);
        __nv_bfloat16 ho[8], lo[8];
        #pragma unroll
        for (int j = 0; j < 8; j++) {
            float v = softplusf(acc[i][j] + bias[n0 + tc * 8 + j]);
            split_bf16(v, ho[j], lo[j]);
        }
        *reinterpret_cast<uint4*>(Chi + m * N + n0 + tc * 8) = *reinterpret_cast<uint4*>(ho);
        *reinterpret_cast<uint4*>(Clo + m * N + n0 + tc * 8) = *reinterpret_cast<uint4*>(lo);
    }
}

// ---------------- depthwise conv + silu, float4 (thread = 4 channels) ------------
__global__ __launch_bounds__(256)
void conv_silu_kernel(const float* __restrict__ cw, const float* __restrict__ cb)
{
    int g = blockIdx.x * 256 + threadIdx.x;    // group index over SEQ*128
    int t  = g >> 7;
    int d4 = (g & 127) * 4;
    const float* xs = g_xr + (size_t)t * 1024 + d4;
    float4 r0 = *reinterpret_cast<const float4*>(xs);
    float4 r1 = (t >= 1) ? *reinterpret_cast<const float4*>(xs - 1024) : make_float4(0,0,0,0);
    float4 r2 = (t >= 2) ? *reinterpret_cast<const float4*>(xs - 2048) : make_float4(0,0,0,0);
    float4 r3 = (t >= 3) ? *reinterpret_cast<const float4*>(xs - 3072) : make_float4(0,0,0,0);
    float4 bv = *reinterpret_cast<const float4*>(cb + d4);

    float u[4];
    const float* c0 = &r0.x; const float* c1 = &r1.x;
    const float* c2 = &r2.x; const float* c3 = &r3.x;
    const float* bb = &bv.x;
    #pragma unroll
    for (int j = 0; j < 4; j++) {
        float4 w = reinterpret_cast<const float4*>(cw)[d4 + j];
        float a = bb[j];
        a = fmaf(w.w, c0[j], a);
        a = fmaf(w.z, c1[j], a);
        a = fmaf(w.y, c2[j], a);
        a = fmaf(w.x, c3[j], a);
        u[j] = siluf(a);
    }
    size_t o = (size_t)t * 512 + d4;
    *reinterpret_cast<float4*>(g_u + o) = make_float4(u[0], u[1], u[2], u[3]);
    __nv_bfloat16 h[4], l[4];
    #pragma unroll
    for (int j = 0; j < 4; j++) split_bf16(u[j], h[j], l[j]);
    *reinterpret_cast<uint2*>(g_uh + o) = *reinterpret_cast<uint2*>(h);
    *reinterpret_cast<uint2*>(g_ul + o) = *reinterpret_cast<uint2*>(l);
}

// ---------------- scan passes (TCH=64, thread = 4 channels) ----------------------
__global__ __launch_bounds__(128)
void scanA_kernel(const float* __restrict__ Alog)
{
    int c  = blockIdx.x;
    int d4 = threadIdx.x * 4;
    float A0[4], A1[4], P0[4], P1[4], S0[4], S1[4];
    #pragma unroll
    for (int j = 0; j < 4; j++) {
        A0[j] = -expf(Alog[(d4 + j) * 2 + 0]);
        A1[j] = -expf(Alog[(d4 + j) * 2 + 1]);
        P0[j] = 1.f; P1[j] = 1.f; S0[j] = 0.f; S1[j] = 0.f;
    }
    const float* dp = g_dp + (size_t)c * TCH * DM + d4;
    const float* uu = g_u  + (size_t)c * TCH * DM + d4;
    const float* xd = g_xdbl + (size_t)c * TCH * 36;
    #pragma unroll 4
    for (int i = 0; i < TCH; i++) {
        float4 dpv = *reinterpret_cast<const float4*>(dp + (size_t)i * DM);
        float4 uv  = *reinterpret_cast<const float4*>(uu + (size_t)i * DM);
        float B0 = xd[i * 36 + 32], B1 = xd[i * 36 + 33];
        const float* dj = &dpv.x; const float* uj = &uv.x;
        #pragma unroll
        for (int j = 0; j < 4; j++) {
            float x0 = dj[j] * A0[j], x1 = dj[j] * A1[j];
            float a0 = 0.f, a1 = 0.f;
            if (fmaxf(x0, x1) > -87.0f) { a0 = __expf(x0); a1 = __expf(x1); }
            float bu = dj[j] * uj[j];
            S0[j] = fmaf(a0, S0[j], bu * B0);
            S1[j] = fmaf(a1, S1[j], bu * B1);
            P0[j] *= a0; P1[j] *= a1;
        }
    }
    #pragma unroll
    for (int j = 0; j < 4; j++) {
        int dn = (d4 + j) * 2;
        g_P[c * 1024 + dn] = P0[j]; g_P[c * 1024 + dn + 1] = P1[j];
        g_S[c * 1024 + dn] = S0[j]; g_S[c * 1024 + dn + 1] = S1[j];
    }
}

__global__ __launch_bounds__(128)
void scanB_kernel()
{
    int dn = blockIdx.x * 128 + threadIdx.x;
    float h = 0.0f;
    for (int cb = 0; cb < NCH; cb += 16) {
        float p[16], s[16];
        #pragma unroll
        for (int i = 0; i < 16; i++) {
            p[i] = g_P[(cb + i) * 1024 + dn];
            s[i] = g_S[(cb + i) * 1024 + dn];
        }
        #pragma unroll
        for (int i = 0; i < 16; i++) {
            g_H[(cb + i) * 1024 + dn] = h;
            h = fmaf(p[i], h, s[i]);
        }
    }
}

__global__ __launch_bounds__(128)
void scanC_kernel(const float* __restrict__ Alog, const float* __restrict__ Dw)
{
    int c  = blockIdx.x;
    int d4 = threadIdx.x * 4;
    float A0[4], A1[4], h0[4], h1[4];
    #pragma unroll
    for (int j = 0; j < 4; j++) {
        A0[j] = -expf(Alog[(d4 + j) * 2 + 0]);
        A1[j] = -expf(Alog[(d4 + j) * 2 + 1]);
        h0[j] = g_H[c * 1024 + (d4 + j) * 2];
        h1[j] = g_H[c * 1024 + (d4 + j) * 2 + 1];
    }
    float4 Dv4 = *reinterpret_cast<const float4*>(Dw + d4);
    const float* Dv = &Dv4.x;
    const float* dp = g_dp + (size_t)c * TCH * DM + d4;
    const float* uu = g_u  + (size_t)c * TCH * DM + d4;
    const float* xd = g_xdbl + (size_t)c * TCH * 36;
    const float* rs = g_xr + (size_t)c * TCH * 1024 + 512 + d4;
    __nv_bfloat16* yh = g_yh + (size_t)c * TCH * DM + d4;
    __nv_bfloat16* yl = g_yl + (size_t)c * TCH * DM + d4;
    #pragma unroll 4
    for (int i = 0; i < TCH; i++) {
        float4 dpv = *reinterpret_cast<const float4*>(dp + (size_t)i * DM);
        float4 uv  = *reinterpret_cast<const float4*>(uu + (size_t)i * DM);
        float4 rv  = *reinterpret_cast<const float4*>(rs + (size_t)i * 1024);
        float B0 = xd[i * 36 + 32], B1 = xd[i * 36 + 33];
        float C0 = xd[i * 36 + 34], C1 = xd[i * 36 + 35];
        const float* dj = &dpv.x; const float* uj = &uv.x; const float* rj = &rv.x;
        __nv_bfloat16 oh[4], ol[4];
        #pragma unroll
        for (int j = 0; j < 4; j++) {
            float x0 = dj[j] * A0[j], x1 = dj[j] * A1[j];
            float a0 = 0.f, a1 = 0.f;
            if (fmaxf(x0, x1) > -87.0f) { a0 = __expf(x0); a1 = __expf(x1); }
            float bu = dj[j] * uj[j];
            h0[j] = fmaf(a0, h0[j], bu * B0);
            h1[j] = fmaf(a1, h1[j], bu * B1);
            float y = fmaf(h0[j], C0, fmaf(h1[j], C1, uj[j] * Dv[j]));
            y *= siluf(rj[j]);
            split_bf16(y, oh[j], ol[j]);
        }
        *reinterpret_cast<uint2*>(yh + (size_t)i * DM) = *reinterpret_cast<uint2*>(oh);
        *reinterpret_cast<uint2*>(yl + (size_t)i * DM) = *reinterpret_cast<uint2*>(ol);
    }
}

// ---------------- launch --------------------------------------------------------
extern "C" void kernel_launch(void* const* d_in, const int* in_sizes, int n_in,
                              void* d_out, int out_size)
{
    const float* x     = (const float*)d_in[0];
    const float* dis   = (const float*)d_in[1];
    const float* inw   = (const float*)d_in[2];
    const float* convw = (const float*)d_in[3];
    const float* convb = (const float*)d_in[4];
    const float* xpw   = (const float*)d_in[5];
    const float* dtw   = (const float*)d_in[6];
    const float* dtb   = (const float*)d_in[7];
    const float* alog  = (const float*)d_in[8];
    const float* Dw    = (const float*)d_in[9];
    const float* outw  = (const float*)d_in[10];
    float* out = (float*)d_out;

    float *xr, *dp, *xdbl;
    __nv_bfloat16 *xh, *xl, *uh, *ul, *dh, *dl, *yh, *yl;
    __nv_bfloat16 *wih, *wil, *dsh, *dsl, *woh, *wol, *xph, *xpl;
    cudaGetSymbolAddress((void**)&xr,   g_xr);
    cudaGetSymbolAddress((void**)&dp,   g_dp);
    cudaGetSymbolAddress((void**)&xdbl, g_xdbl);
    cudaGetSymbolAddress((void**)&xh,  g_xh);  cudaGetSymbolAddress((void**)&xl,  g_xl);
    cudaGetSymbolAddress((void**)&uh,  g_uh);  cudaGetSymbolAddress((void**)&ul,  g_ul);
    cudaGetSymbolAddress((void**)&dh,  g_dh);  cudaGetSymbolAddress((void**)&dl,  g_dl);
    cudaGetSymbolAddress((void**)&yh,  g_yh);  cudaGetSymbolAddress((void**)&yl,  g_yl);
    cudaGetSymbolAddress((void**)&wih, g_wih); cudaGetSymbolAddress((void**)&wil, g_wil);
    cudaGetSymbolAddress((void**)&dsh, g_dsh); cudaGetSymbolAddress((void**)&dsl, g_dsl);
    cudaGetSymbolAddress((void**)&woh, g_woh); cudaGetSymbolAddress((void**)&wol, g_wol);
    cudaGetSymbolAddress((void**)&xph, g_xph); cudaGetSymbolAddress((void**)&xpl, g_xpl);

    const int GEMM_SMEM = 2 * STAGE_B;   // 81920
    cudaFuncSetAttribute(mma_gemm<0>, cudaFuncAttributeMaxDynamicSharedMemorySize, GEMM_SMEM);
    cudaFuncSetAttribute(mma_gemm<1>, cudaFuncAttributeMaxDynamicSharedMemorySize, GEMM_SMEM);
    cudaFuncSetAttribute(mma_gemm<2>, cudaFuncAttributeMaxDynamicSharedMemorySize, GEMM_SMEM);

    // 0) all split conversions
    cvt_all<<<18432, 256>>>(x, inw, outw, dis, xpw);

    // 1) xr = x @ in_proj_w^T   [32768 x 1024]
    mma_gemm<0><<<dim3(8, SEQ / 128), 256, GEMM_SMEM>>>(xh, xl, wih, wil, xr, 1024, 512, 1024);

    // 2) u = silu(conv(xs))  (+ bf16 split), float4
    conv_silu_kernel<<<(SEQ * 128) / 256, 256>>>(convw, convb);

    // 3) xdbl = u @ x_proj_w^T  (tensor core, N padded to 128, store cols<36)
    mma_gemm<2><<<dim3(1, SEQ / 128), 256, GEMM_SMEM>>>(uh, ul, xph, xpl, xdbl, 128, 512, 36);

    // 4) delta = softplus(xdbl[:, :32] @ dt_proj_w^T + b) -> bf16 split
    dtproj_kernel<<<dim3(DM / 128, SEQ / 128), 256>>>(g_xdbl, dtw, dtb, dh, dl);

    // 5) delta_p = delta @ dis_dense  (dis pre-transposed to [N,K])
    mma_gemm<0><<<dim3(DM / 128, SEQ / 128), 256, GEMM_SMEM>>>(dh, dl, dsh, dsl, dp, DM, 512, DM);

    // 6-8) chunked selective scan (512 chunks of 64)
    scanA_kernel<<<NCH, 128>>>(alog);
    scanB_kernel<<<8, 128>>>();
    scanC_kernel<<<NCH, 128>>>(alog, Dw);

    // 9) out = y @ out_proj_w^T, finite filter
    mma_gemm<1><<<dim3(DM / 128, SEQ / 128), 256, GEMM_SMEM>>>(yh, yl, woh, wol, out, DM, 512, DM);
}

// round 8
// speedup vs baseline: 1.2440x; 1.0900x over previous
#include <cuda_runtime.h>
#include <cuda_bf16.h>
#include <math.h>
#include <stdint.h>

#define SEQ   32768
#define DM    512
#define NCH   512
#define TCH   64
#define C_LN2 0.69314718055994531f

// ---------------- scratch (device globals) -----------------------------------
__device__ float g_xr  [(size_t)SEQ * 1024];   // in_proj output (xs | res)
__device__ float g_u   [(size_t)SEQ * DM];     // conv+silu output
__device__ float g_xdbl[(size_t)SEQ * 36];     // x_proj output
__device__ float g_dp  [(size_t)SEQ * DM];     // delta_p
__device__ float g_P   [NCH * 1024];
__device__ float g_S   [NCH * 1024];
__device__ float g_H   [NCH * 1024];
__device__ float g_csum[DM];                   // ln2 * colsum(dis)

// bf16 split operands for tensor GEMMs
__device__ __nv_bfloat16 g_xh [(size_t)SEQ * DM], g_xl [(size_t)SEQ * DM];
__device__ __nv_bfloat16 g_uh [(size_t)SEQ * DM], g_ul [(size_t)SEQ * DM];
__device__ __nv_bfloat16 g_dh [(size_t)SEQ * DM];                        // delta residual
__device__ __nv_bfloat16 g_yh [(size_t)SEQ * DM], g_yl [(size_t)SEQ * DM];
__device__ __nv_bfloat16 g_wih[1024 * 512],       g_wil[1024 * 512];
__device__ __nv_bfloat16 g_dsh[512 * 512],        g_dsl[512 * 512];      // dis^T
__device__ __nv_bfloat16 g_woh[512 * 512],        g_wol[512 * 512];
__device__ __nv_bfloat16 g_xph[128 * 512],        g_xpl[128 * 512];      // x_proj_w padded

// ---------------- PTX helpers ---------------------------------------------------
__device__ __forceinline__ uint32_t smem_u32(const void* p) {
    uint32_t a;
    asm("{ .reg .u64 t; cvta.to.shared.u64 t, %1; cvt.u32.u64 %0, t; }" : "=r"(a) : "l"(p));
    return a;
}
#define CP_ASYNC16(dst, src) \
    asm volatile("cp.async.cg.shared.global [%0], [%1], 16;" :: "r"(dst), "l"(src) : "memory")
#define CP_COMMIT() asm volatile("cp.async.commit_group;" ::: "memory")
#define CP_WAIT1()  asm volatile("cp.async.wait_group 1;" ::: "memory")

__device__ __forceinline__ void ldsm4(uint32_t* r, uint32_t addr) {
    asm volatile("ldmatrix.sync.aligned.m8n8.x4.shared.b16 {%0,%1,%2,%3}, [%4];"
                 : "=r"(r[0]), "=r"(r[1]), "=r"(r[2]), "=r"(r[3]) : "r"(addr));
}
__device__ __forceinline__ void mma16816(float* c, const uint32_t* a,
                                         uint32_t b0, uint32_t b1) {
    asm volatile("mma.sync.aligned.m16n8k16.row.col.f32.bf16.bf16.f32 "
                 "{%0,%1,%2,%3}, {%4,%5,%6,%7}, {%8,%9}, {%0,%1,%2,%3};"
                 : "+f"(c[0]), "+f"(c[1]), "+f"(c[2]), "+f"(c[3])
                 : "r"(a[0]), "r"(a[1]), "r"(a[2]), "r"(a[3]), "r"(b0), "r"(b1));
}

// ---------------- math helpers --------------------------------------------------
__device__ __forceinline__ float softplusf(float x) {
    float ax = fabsf(x);
    if (ax < 0.25f) {
        float x2 = x * x;
        return C_LN2 + 0.5f * x
             + x2 * (0.125f + x2 * (-1.0f/192.0f + x2 * (1.0f/2880.0f)));
    }
    return fmaxf(x, 0.0f) + log1pf(expf(-ax));
}
__device__ __forceinline__ float siluf(float x) { return x / (1.0f + __expf(-x)); }
__device__ __forceinline__ void split_bf16(float v, __nv_bfloat16& h, __nv_bfloat16& l) {
    h = __float2bfloat16(v);
    l = __float2bfloat16(v - __bfloat162float(h));
}

// ---------------- combined split conversion kernel ------------------------------
__global__ __launch_bounds__(256)
void cvt_all(const float* __restrict__ x, const float* __restrict__ inw,
             const float* __restrict__ outw, const float* __restrict__ dis,
             const float* __restrict__ xpw)
{
    int b = blockIdx.x;
    if (b < 16384) {
        int i = b * 256 + threadIdx.x;
        float4 v = reinterpret_cast<const float4*>(x)[i];
        __nv_bfloat16 h[4], l[4];
        split_bf16(v.x, h[0], l[0]); split_bf16(v.y, h[1], l[1]);
        split_bf16(v.z, h[2], l[2]); split_bf16(v.w, h[3], l[3]);
        reinterpret_cast<uint2*>(g_xh)[i] = *reinterpret_cast<uint2*>(h);
        reinterpret_cast<uint2*>(g_xl)[i] = *reinterpret_cast<uint2*>(l);
    } else if (b < 16896) {
        int i = (b - 16384) * 256 + threadIdx.x;
        float4 v = reinterpret_cast<const float4*>(inw)[i];
        __nv_bfloat16 h[4], l[4];
        split_bf16(v.x, h[0], l[0]); split_bf16(v.y, h[1], l[1]);
        split_bf16(v.z, h[2], l[2]); split_bf16(v.w, h[3], l[3]);
        reinterpret_cast<uint2*>(g_wih)[i] = *reinterpret_cast<uint2*>(h);
        reinterpret_cast<uint2*>(g_wil)[i] = *reinterpret_cast<uint2*>(l);
    } else if (b < 17152) {
        int i = (b - 16896) * 256 + threadIdx.x;
        float4 v = reinterpret_cast<const float4*>(outw)[i];
        __nv_bfloat16 h[4], l[4];
        split_bf16(v.x, h[0], l[0]); split_bf16(v.y, h[1], l[1]);
        split_bf16(v.z, h[2], l[2]); split_bf16(v.w, h[3], l[3]);
        reinterpret_cast<uint2*>(g_woh)[i] = *reinterpret_cast<uint2*>(h);
        reinterpret_cast<uint2*>(g_wol)[i] = *reinterpret_cast<uint2*>(l);
    } else if (b < 18176) {
        int idx = (b - 17152) * 256 + threadIdx.x;   // out[n][k] = dis[k][n]
        int n = idx >> 9, k = idx & 511;
        __nv_bfloat16 h, l;
        split_bf16(dis[k * 512 + n], h, l);
        g_dsh[idx] = h; g_dsl[idx] = l;
    } else {
        int idx = (b - 18176) * 256 + threadIdx.x;   // 128x512 padded
        int r = idx >> 9;
        __nv_bfloat16 h = __float2bfloat16(0.0f), l = h;
        if (r < 36) split_bf16(xpw[idx], h, l);
        g_xph[idx] = h; g_xpl[idx] = l;
    }
}

// ---------------- colsum of dis (for rank-1 delta_p term) ------------------------
__global__ __launch_bounds__(256)
void colsum_kernel(const float* __restrict__ dis)
{
    int n = blockIdx.x * 256 + threadIdx.x;   // grid=2
    float s = 0.0f;
    #pragma unroll 8
    for (int k = 0; k < 512; k++) s += dis[k * 512 + n];
    g_csum[n] = s * C_LN2;
}

// ---------------- mma.sync bf16 GEMM ---------------------------------------------
// TERMS=3: C = (Ah+Al)@(Bh+Bl)^T (3-term split).  TERMS=1: C = Ah@Bh^T.
// CTA tile 128m x 128n, BK=32, 2-stage cp.async, 8 warps (4m x 2n), warp 32x64.
// EPI: 0 plain, 1 finite filter, 2 narrow store (cols<ldc), 3 += bias2[col]
#define PITCH   80
#define STAGE_B 40960
template <int EPI, int TERMS>
__global__ __launch_bounds__(256, 2)
void mma_gemm(const __nv_bfloat16* __restrict__ Ah, const __nv_bfloat16* __restrict__ Al,
              const __nv_bfloat16* __restrict__ Bh, const __nv_bfloat16* __restrict__ Bl,
              float* __restrict__ C, const float* __restrict__ bias2,
              int N, int K, int ldc)
{
    extern __shared__ char dsm[];
    const uint32_t sb = smem_u32(dsm);
    const int tid = threadIdx.x;
    const int wid = tid >> 5, L = tid & 31;
    const int wm = wid >> 1, wn = wid & 1;
    const int m0 = blockIdx.y * 128, n0 = blockIdx.x * 128;

    const __nv_bfloat16* srcA[2] = { Ah + (size_t)m0 * K,
                                     (TERMS == 3 ? Al : Ah) + (size_t)m0 * K };
    const __nv_bfloat16* srcB[2] = { Bh + (size_t)n0 * K,
                                     (TERMS == 3 ? Bl : Bh) + (size_t)n0 * K };

    const int lrow = L & 15;
    const int lcolB = (L >> 4) * 16;
    const uint32_t aBase = sb + (wm * 32 + lrow) * PITCH + lcolB;
    const uint32_t bBase = sb + 20480 + (wn * 64 + lrow) * PITCH + lcolB;

    float acc[2][8][4];
    #pragma unroll
    for (int i = 0; i < 2; i++)
        #pragma unroll
        for (int j = 0; j < 8; j++)
            #pragma unroll
            for (int q = 0; q < 4; q++) acc[i][j][q] = 0.0f;

    const int nk = K / 32;

    auto load_stage = [&](int ks, int buf) {
        uint32_t dst0 = sb + buf * STAGE_B;
        int k0 = ks * 32;
        if (TERMS == 3) {
            #pragma unroll
            for (int it = 0; it < 8; it++) {
                int cid = it * 256 + tid;
                int mat = cid >> 9, w = cid & 511;
                int r = w >> 2, c = w & 3;
                uint32_t dst = dst0 + mat * 10240 + r * PITCH + c * 16;
                const __nv_bfloat16* src =
                    (mat < 2 ? srcA[mat] : srcB[mat - 2]) + (size_t)r * K + k0 + c * 8;
                CP_ASYNC16(dst, src);
            }
        } else {
            #pragma unroll
            for (int it = 0; it < 4; it++) {
                int cid = it * 256 + tid;
                int isB = cid >> 9, w = cid & 511;
                int r = w >> 2, c = w & 3;
                uint32_t dst = dst0 + isB * 20480 + r * PITCH + c * 16;
                const __nv_bfloat16* src =
                    (isB ? srcB[0] : srcA[0]) + (size_t)r * K + k0 + c * 8;
                CP_ASYNC16(dst, src);
            }
        }
    };

    load_stage(0, 0); CP_COMMIT();
    load_stage(1, 1); CP_COMMIT();

    for (int ks = 0; ks < nk; ks++) {
        CP_WAIT1();
        __syncthreads();
        uint32_t bo = (ks & 1) * STAGE_B;
        #pragma unroll
        for (int kk = 0; kk < 2; kk++) {
            uint32_t ko = kk * 32;
            uint32_t ah[2][4], al[2][4], b[4][4];
            #pragma unroll
            for (int mi = 0; mi < 2; mi++) {
                ldsm4(ah[mi], aBase + bo + mi * 1280 + ko);
                if (TERMS == 3) ldsm4(al[mi], aBase + bo + 10240 + mi * 1280 + ko);
            }
            #pragma unroll
            for (int t = 0; t < 4; t++)
                ldsm4(b[t], bBase + bo + t * 1280 + ko);
            #pragma unroll
            for (int mi = 0; mi < 2; mi++)
                #pragma unroll
                for (int t = 0; t < 4; t++) {
                    mma16816(acc[mi][2*t+0], ah[mi], b[t][0], b[t][2]);
                    mma16816(acc[mi][2*t+1], ah[mi], b[t][1], b[t][3]);
                    if (TERMS == 3) {
                        mma16816(acc[mi][2*t+0], al[mi], b[t][0], b[t][2]);
                        mma16816(acc[mi][2*t+1], al[mi], b[t][1], b[t][3]);
                    }
                }
            if (TERMS == 3) {
                #pragma unroll
                for (int t = 0; t < 4; t++)
                    ldsm4(b[t], bBase + bo + 10240 + t * 1280 + ko);
                #pragma unroll
                for (int mi = 0; mi < 2; mi++)
                    #pragma unroll
                    for (int t = 0; t < 4; t++) {
                        mma16816(acc[mi][2*t+0], ah[mi], b[t][0], b[t][2]);
                        mma16816(acc[mi][2*t+1], ah[mi], b[t][1], b[t][3]);
                    }
            }
        }
        __syncthreads();
        if (ks + 2 < nk) load_stage(ks + 2, ks & 1);
        CP_COMMIT();
    }

    // epilogue
    #pragma unroll
    for (int mi = 0; mi < 2; mi++) {
        #pragma unroll
        for (int j = 0; j < 8; j++) {
            int row = m0 + wm * 32 + mi * 16 + (L >> 2);
            int col = n0 + wn * 64 + j * 8 + (L & 3) * 2;
            float v0 = acc[mi][j][0], v1 = acc[mi][j][1];
            float v2 = acc[mi][j][2], v3 = acc[mi][j][3];
            if (EPI == 1) {
                v0 = isfinite(v0) ? v0 : 0.0f; v1 = isfinite(v1) ? v1 : 0.0f;
                v2 = isfinite(v2) ? v2 : 0.0f; v3 = isfinite(v3) ? v3 : 0.0f;
            }
            if (EPI == 3) {
                float b0 = bias2[col], b1 = bias2[col + 1];
                v0 += b0; v1 += b1; v2 += b0; v3 += b1;
            }
            if (EPI == 2) {
                if (col + 1 < ldc) {
                    *reinterpret_cast<float2*>(C + (size_t)row * ldc + col)       = make_float2(v0, v1);
                    *reinterpret_cast<float2*>(C + (size_t)(row + 8) * ldc + col) = make_float2(v2, v3);
                }
            } else {
                *reinterpret_cast<float2*>(C + (size_t)row * ldc + col)       = make_float2(v0, v1);
                *reinterpret_cast<float2*>(C + (size_t)(row + 8) * ldc + col) = make_float2(v2, v3);
            }
        }
    }
}

// ---------------- SIMT GEMM (dt_proj: K=32, softplus, bf16 residual output) -----
__global__ __launch_bounds__(256)
void dtproj_kernel(const float* __restrict__ A,      // g_xdbl, lda=36
                   const float* __restrict__ B,      // dt_proj_w [512,32]
                   const float* __restrict__ bias,
                   __nv_bfloat16* __restrict__ Chi)
{
    __shared__ float As[8][128];
    __shared__ float Bs[8][128];
    const int tid = threadIdx.x;
    const int m0 = blockIdx.y * 128, n0 = blockIdx.x * 128;
    const int tr = tid / 16, tc = tid % 16;
    const int K = 32, N = 512, lda = 36;

    float acc[8][8];
    #pragma unroll
    for (int i = 0; i < 8; i++)
        #pragma unroll
        for (int j = 0; j < 8; j++) acc[i][j] = 0.0f;

    for (int k0 = 0; k0 < K; k0 += 8) {
        {
            int row = tid >> 1, kq = (tid & 1) * 4;
            float4 v = *reinterpret_cast<const float4*>(A + (size_t)(m0 + row) * lda + k0 + kq);
            As[kq+0][row] = v.x; As[kq+1][row] = v.y; As[kq+2][row] = v.z; As[kq+3][row] = v.w;
        }
        {
            int row = tid >> 1, kq = (tid & 1) * 4;
            float4 v = *reinterpret_cast<const float4*>(B + (size_t)(n0 + row) * K + k0 + kq);
            Bs[kq+0][row] = v.x; Bs[kq+1][row] = v.y; Bs[kq+2][row] = v.z; Bs[kq+3][row] = v.w;
        }
        __syncthreads();
        #pragma unroll
        for (int k = 0; k < 8; k++) {
            float ra[8], rb[8];
            *reinterpret_cast<float4*>(&ra[0]) = *reinterpret_cast<const float4*>(&As[k][tr*8]);
            *reinterpret_cast<float4*>(&ra[4]) = *reinterpret_cast<const float4*>(&As[k][tr*8+4]);
            *reinterpret_cast<float4*>(&rb[0]) = *reinterpret_cast<const float4*>(&Bs[k][tc*8]);
            *reinterpret_cast<float4*>(&rb[4]) = *reinterpret_cast<const float4*>(&Bs[k][tc*8+4]);
            #pragma unroll
            for (int i = 0; i < 8; i++)
                #pragma unroll
                for (int j = 0; j < 8; j++)
                    acc[i][j] = fmaf(ra[i], rb[j], acc[i][j]);
        }
        __syncthreads();
    }
    #pragma unroll
    for (int i = 0; i < 8; i++) {
        size_t m = (size_t)(m0 + tr * 8 + i);
        __nv_bfloat16 ho[8];
        #pragma unroll
        for (int j = 0; j < 8; j++) {
            float v = softplusf(acc[i][j] + bias[n0 + tc * 8 + j]) - C_LN2;
            ho[j] = __float2bfloat16(v);
        }
        *reinterpret_cast<uint4*>(Chi + m * N + n0 + tc * 8) = *reinterpret_cast<uint4*>(ho);
    }
}

// ---------------- depthwise conv + silu, float4 (thread = 4 channels) ------------
__global__ __launch_bounds__(256)
void conv_silu_kernel(const float* __restrict__ cw, const float* __restrict__ cb)
{
    int g = blockIdx.x * 256 + threadIdx.x;
    int t  = g >> 7;
    int d4 = (g & 127) * 4;
    const float* xs = g_xr + (size_t)t * 1024 + d4;
    float4 r0 = *reinterpret_cast<const float4*>(xs);
    float4 r1 = (t >= 1) ? *reinterpret_cast<const float4*>(xs - 1024) : make_float4(0,0,0,0);
    float4 r2 = (t >= 2) ? *reinterpret_cast<const float4*>(xs - 2048) : make_float4(0,0,0,0);
    float4 r3 = (t >= 3) ? *reinterpret_cast<const float4*>(xs - 3072) : make_float4(0,0,0,0);
    float4 bv = *reinterpret_cast<const float4*>(cb + d4);

    float u[4];
    const float* c0 = &r0.x; const float* c1 = &r1.x;
    const float* c2 = &r2.x; const float* c3 = &r3.x;
    const float* bb = &bv.x;
    #pragma unroll
    for (int j = 0; j < 4; j++) {
        float4 w = reinterpret_cast<const float4*>(cw)[d4 + j];
        float a = bb[j];
        a = fmaf(w.w, c0[j], a);
        a = fmaf(w.z, c1[j], a);
        a = fmaf(w.y, c2[j], a);
        a = fmaf(w.x, c3[j], a);
        u[j] = siluf(a);
    }
    size_t o = (size_t)t * 512 + d4;
    *reinterpret_cast<float4*>(g_u + o) = make_float4(u[0], u[1], u[2], u[3]);
    __nv_bfloat16 h[4], l[4];
    #pragma unroll
    for (int j = 0; j < 4; j++) split_bf16(u[j], h[j], l[j]);
    *reinterpret_cast<uint2*>(g_uh + o) = *reinterpret_cast<uint2*>(h);
    *reinterpret_cast<uint2*>(g_ul + o) = *reinterpret_cast<uint2*>(l);
}

// ---------------- scan passes (TCH=64, thread = 4 channels) ----------------------
__global__ __launch_bounds__(128)
void scanA_kernel(const float* __restrict__ Alog)
{
    int c  = blockIdx.x;
    int d4 = threadIdx.x * 4;
    float A0[4], A1[4], P0[4], P1[4], S0[4], S1[4];
    #pragma unroll
    for (int j = 0; j < 4; j++) {
        A0[j] = -expf(Alog[(d4 + j) * 2 + 0]);
        A1[j] = -expf(Alog[(d4 + j) * 2 + 1]);
        P0[j] = 1.f; P1[j] = 1.f; S0[j] = 0.f; S1[j] = 0.f;
    }
    const float* dp = g_dp + (size_t)c * TCH * DM + d4;
    const float* uu = g_u  + (size_t)c * TCH * DM + d4;
    const float* xd = g_xdbl + (size_t)c * TCH * 36;
    #pragma unroll 4
    for (int i = 0; i < TCH; i++) {
        float4 dpv = *reinterpret_cast<const float4*>(dp + (size_t)i * DM);
        float4 uv  = *reinterpret_cast<const float4*>(uu + (size_t)i * DM);
        float B0 = xd[i * 36 + 32], B1 = xd[i * 36 + 33];
        const float* dj = &dpv.x; const float* uj = &uv.x;
        #pragma unroll
        for (int j = 0; j < 4; j++) {
            float x0 = dj[j] * A0[j], x1 = dj[j] * A1[j];
            float a0 = 0.f, a1 = 0.f;
            if (fmaxf(x0, x1) > -87.0f) { a0 = __expf(x0); a1 = __expf(x1); }
            float bu = dj[j] * uj[j];
            S0[j] = fmaf(a0, S0[j], bu * B0);
            S1[j] = fmaf(a1, S1[j], bu * B1);
            P0[j] *= a0; P1[j] *= a1;
        }
    }
    #pragma unroll
    for (int j = 0; j < 4; j++) {
        int dn = (d4 + j) * 2;
        g_P[c * 1024 + dn] = P0[j]; g_P[c * 1024 + dn + 1] = P1[j];
        g_S[c * 1024 + dn] = S0[j]; g_S[c * 1024 + dn + 1] = S1[j];
    }
}

__global__ __launch_bounds__(128)
void scanB_kernel()
{
    int dn = blockIdx.x * 128 + threadIdx.x;
    float h = 0.0f;
    for (int cb = 0; cb < NCH; cb += 16) {
        float p[16], s[16];
        #pragma unroll
        for (int i = 0; i < 16; i++) {
            p[i] = g_P[(cb + i) * 1024 + dn];
            s[i] = g_S[(cb + i) * 1024 + dn];
        }
        #pragma unroll
        for (int i = 0; i < 16; i++) {
            g_H[(cb + i) * 1024 + dn] = h;
            h = fmaf(p[i], h, s[i]);
        }
    }
}

__global__ __launch_bounds__(128)
void scanC_kernel(const float* __restrict__ Alog, const float* __restrict__ Dw)
{
    int c  = blockIdx.x;
    int d4 = threadIdx.x * 4;
    float A0[4], A1[4], h0[4], h1[4];
    #pragma unroll
    for (int j = 0; j < 4; j++) {
        A0[j] = -expf(Alog[(d4 + j) * 2 + 0]);
        A1[j] = -expf(Alog[(d4 + j) * 2 + 1]);
        h0[j] = g_H[c * 1024 + (d4 + j) * 2];
        h1[j] = g_H[c * 1024 + (d4 + j) * 2 + 1];
    }
    float4 Dv4 = *reinterpret_cast<const float4*>(Dw + d4);
    const float* Dv = &Dv4.x;
    const float* dp = g_dp + (size_t)c * TCH * DM + d4;
    const float* uu = g_u  + (size_t)c * TCH * DM + d4;
    const float* xd = g_xdbl + (size_t)c * TCH * 36;
    const float* rs = g_xr + (size_t)c * TCH * 1024 + 512 + d4;
    __nv_bfloat16* yh = g_yh + (size_t)c * TCH * DM + d4;
    __nv_bfloat16* yl = g_yl + (size_t)c * TCH * DM + d4;
    #pragma unroll 4
    for (int i = 0; i < TCH; i++) {
        float4 dpv = *reinterpret_cast<const float4*>(dp + (size_t)i * DM);
        float4 uv  = *reinterpret_cast<const float4*>(uu + (size_t)i * DM);
        float4 rv  = *reinterpret_cast<const float4*>(rs + (size_t)i * 1024);
        float B0 = xd[i * 36 + 32], B1 = xd[i * 36 + 33];
        float C0 = xd[i * 36 + 34], C1 = xd[i * 36 + 35];
        const float* dj = &dpv.x; const float* uj = &uv.x; const float* rj = &rv.x;
        __nv_bfloat16 oh[4], ol[4];
        #pragma unroll
        for (int j = 0; j < 4; j++) {
            float x0 = dj[j] * A0[j], x1 = dj[j] * A1[j];
            float a0 = 0.f, a1 = 0.f;
            if (fmaxf(x0, x1) > -87.0f) { a0 = __expf(x0); a1 = __expf(x1); }
            float bu = dj[j] * uj[j];
            h0[j] = fmaf(a0, h0[j], bu * B0);
            h1[j] = fmaf(a1, h1[j], bu * B1);
            float y = fmaf(h0[j], C0, fmaf(h1[j], C1, uj[j] * Dv[j]));
            y *= siluf(rj[j]);
            split_bf16(y, oh[j], ol[j]);
        }
        *reinterpret_cast<uint2*>(yh + (size_t)i * DM) = *reinterpret_cast<uint2*>(oh);
        *reinterpret_cast<uint2*>(yl + (size_t)i * DM) = *reinterpret_cast<uint2*>(ol);
    }
}

// ---------------- launch --------------------------------------------------------
extern "C" void kernel_launch(void* const* d_in, const int* in_sizes, int n_in,
                              void* d_out, int out_size)
{
    const float* x     = (const float*)d_in[0];
    const float* dis   = (const float*)d_in[1];
    const float* inw   = (const float*)d_in[2];
    const float* convw = (const float*)d_in[3];
    const float* convb = (const float*)d_in[4];
    const float* xpw   = (const float*)d_in[5];
    const float* dtw   = (const float*)d_in[6];
    const float* dtb   = (const float*)d_in[7];
    const float* alog  = (const float*)d_in[8];
    const float* Dw    = (const float*)d_in[9];
    const float* outw  = (const float*)d_in[10];
    float* out = (float*)d_out;

    float *xr, *dp, *xdbl, *csum;
    __nv_bfloat16 *xh, *xl, *uh, *ul, *dh, *yh, *yl;
    __nv_bfloat16 *wih, *wil, *dsh, *dsl, *woh, *wol, *xph, *xpl;
    cudaGetSymbolAddress((void**)&xr,   g_xr);
    cudaGetSymbolAddress((void**)&dp,   g_dp);
    cudaGetSymbolAddress((void**)&xdbl, g_xdbl);
    cudaGetSymbolAddress((void**)&csum, g_csum);
    cudaGetSymbolAddress((void**)&xh,  g_xh);  cudaGetSymbolAddress((void**)&xl,  g_xl);
    cudaGetSymbolAddress((void**)&uh,  g_uh);  cudaGetSymbolAddress((void**)&ul,  g_ul);
    cudaGetSymbolAddress((void**)&dh,  g_dh);
    cudaGetSymbolAddress((void**)&yh,  g_yh);  cudaGetSymbolAddress((void**)&yl,  g_yl);
    cudaGetSymbolAddress((void**)&wih, g_wih); cudaGetSymbolAddress((void**)&wil, g_wil);
    cudaGetSymbolAddress((void**)&dsh, g_dsh); cudaGetSymbolAddress((void**)&dsl, g_dsl);
    cudaGetSymbolAddress((void**)&woh, g_woh); cudaGetSymbolAddress((void**)&wol, g_wol);
    cudaGetSymbolAddress((void**)&xph, g_xph); cudaGetSymbolAddress((void**)&xpl, g_xpl);

    const int GEMM_SMEM = 2 * STAGE_B;   // 81920
    cudaFuncSetAttribute((const void*)mma_gemm<0,3>, cudaFuncAttributeMaxDynamicSharedMemorySize, GEMM_SMEM);
    cudaFuncSetAttribute((const void*)mma_gemm<1,3>, cudaFuncAttributeMaxDynamicSharedMemorySize, GEMM_SMEM);
    cudaFuncSetAttribute((const void*)mma_gemm<2,3>, cudaFuncAttributeMaxDynamicSharedMemorySize, GEMM_SMEM);
    cudaFuncSetAttribute((const void*)mma_gemm<3,1>, cudaFuncAttributeMaxDynamicSharedMemorySize, GEMM_SMEM);

    // 0) all split conversions + dis colsum
    cvt_all<<<18432, 256>>>(x, inw, outw, dis, xpw);
    colsum_kernel<<<2, 256>>>(dis);

    // 1) xr = x @ in_proj_w^T   [32768 x 1024]
    mma_gemm<0,3><<<dim3(8, SEQ / 128), 256, GEMM_SMEM>>>(xh, xl, wih, wil, xr, nullptr, 1024, 512, 1024);

    // 2) u = silu(conv(xs))  (+ bf16 split)
    conv_silu_kernel<<<(SEQ * 128) / 256, 256>>>(convw, convb);

    // 3) xdbl = u @ x_proj_w^T  (N padded to 128, store cols<36)
    mma_gemm<2,3><<<dim3(1, SEQ / 128), 256, GEMM_SMEM>>>(uh, ul, xph, xpl, xdbl, nullptr, 128, 512, 36);

    // 4) delta residual = softplus(xdbl[:, :32] @ dt_proj_w^T + b) - ln2 -> bf16
    dtproj_kernel<<<dim3(DM / 128, SEQ / 128), 256>>>(g_xdbl, dtw, dtb, dh);

    // 5) delta_p = ln2*colsum(dis) + residual @ dis  (1-term bf16 GEMM + rank-1)
    mma_gemm<3,1><<<dim3(DM / 128, SEQ / 128), 256, GEMM_SMEM>>>(dh, nullptr, dsh, nullptr, dp, csum, DM, 512, DM);

    // 6-8) chunked selective scan (512 chunks of 64)
    scanA_kernel<<<NCH, 128>>>(alog);
    scanB_kernel<<<8, 128>>>();
    scanC_kernel<<<NCH, 128>>>(alog, Dw);

    // 9) out = y @ out_proj_w^T, finite filter
    mma_gemm<1,3><<<dim3(DM / 128, SEQ / 128), 256, GEMM_SMEM>>>(yh, yl, woh, wol, out, nullptr, DM, 512, DM);
}